// round 6
// baseline (speedup 1.0000x reference)
#include <cuda_runtime.h>
#include <cuda_fp16.h>
#include <math_constants.h>

// Problem constants (fixed by the reference setup)
#define NN    50000
#define EE    1600000
#define DIN   128
#define DOUT  128
#define HH    8
#define DHH   16
#define DGG   64
#define BCOLS 352   // padded: 64 zj | 128 f0 | 128 f1 | 8 fz | 24 pad

// ---------------- device scratch (no allocation allowed) ----------------
__device__ float  g_B[DIN * BCOLS];    // prepacked GEMM B
__device__ __half g_zjh[NN * DGG];     // fp16 feat @ Wpg         [N,64]
__device__ float  g_f0[NN * DOUT];     // relu(feat@W0 + b0)      [N,128]
__device__ __half g_f1h[NN * DOUT];    // fp16 relu(feat@W1+b1)   [N,128]
__device__ __half g_fzh[NN * HH];      // fp16 feat @ wg[192:320] [N,8]
__device__ float  g_aself[NN * HH];    // leaky(f0 . att_self)    [N,8]
__device__ float  g_aneigh[NN * HH];   // leaky(f1 . att_neigh)   [N,8]
__device__ int    g_cnt[NN];
__device__ int    g_ptr[NN + 1];
__device__ int    g_pos[NN];
__device__ unsigned long long g_edge[EE];  // packed (val<<32 | col), CSR order

// ---------------- CSR build ----------------
__global__ void k_zero_cnt() {
    int i = blockIdx.x * blockDim.x + threadIdx.x;
    if (i < NN) g_cnt[i] = 0;
}

__global__ void k_hist(const int* __restrict__ row) {
    int i = blockIdx.x * blockDim.x + threadIdx.x;
    if (i < EE) atomicAdd(&g_cnt[row[i]], 1);
}

__global__ void k_scan() {
    __shared__ int wsum[32];
    __shared__ int s_carry;
    int tid  = threadIdx.x;
    int lane = tid & 31;
    int wid  = tid >> 5;
    if (tid == 0) s_carry = 0;
    __syncthreads();
    for (int base = 0; base < NN; base += 1024) {
        int i = base + tid;
        int x = (i < NN) ? g_cnt[i] : 0;
        int v = x;
        #pragma unroll
        for (int off = 1; off < 32; off <<= 1) {
            int t = __shfl_up_sync(0xffffffffu, v, off);
            if (lane >= off) v += t;
        }
        if (lane == 31) wsum[wid] = v;
        __syncthreads();
        if (wid == 0) {
            int s = wsum[lane];
            #pragma unroll
            for (int off = 1; off < 32; off <<= 1) {
                int t = __shfl_up_sync(0xffffffffu, s, off);
                if (lane >= off) s += t;
            }
            wsum[lane] = s;
        }
        __syncthreads();
        int incl  = v + (wid > 0 ? wsum[wid - 1] : 0);
        int carry = s_carry;
        if (i < NN) {
            int e = carry + incl - x;
            g_ptr[i] = e;
            g_pos[i] = e;
        }
        __syncthreads();
        if (tid == 1023) s_carry = carry + incl;
        __syncthreads();
    }
    if (tid == 0) g_ptr[NN] = s_carry;
}

__global__ void k_scatter(const int* __restrict__ row,
                          const int* __restrict__ col,
                          const float* __restrict__ val) {
    int i = blockIdx.x * blockDim.x + threadIdx.x;
    if (i < EE) {
        int p = atomicAdd(&g_pos[row[i]], 1);
        unsigned long long pk =
            ((unsigned long long)__float_as_uint(val[i]) << 32) |
            (unsigned long long)(unsigned)col[i];
        g_edge[p] = pk;
    }
}

// ---------------- pack B once: [128][352] ----------------
__global__ void k_pack(const float* __restrict__ Wpg,
                       const float* __restrict__ W,
                       const float* __restrict__ wg) {
    int idx = blockIdx.x * blockDim.x + threadIdx.x;
    if (idx >= DIN * BCOLS) return;
    int k = idx / BCOLS, c = idx - k * BCOLS;
    float w = 0.f;
    if (c < DGG) {
        w = Wpg[k * DGG + c];
    } else if (c < 320) {
        int j  = c - DGG;
        int o  = j >> 7;
        int jj = j & 127;
        int h  = jj >> 4, kb = jj & 15;
        w = W[((o * HH + h) * DIN + k) * DHH + kb];
    } else if (c < 328) {
        w = wg[(192 + k) * HH + (c - 320)];
    }
    g_B[idx] = w;
}

// ---------------- GEMM: [N,128] x [128,352] (packed B) ----------------
#define KC 16
__global__ void __launch_bounds__(256, 4)
k_gemm(const float* __restrict__ feat, const float* __restrict__ b) {
    __shared__ float As[32][KC + 1];
    __shared__ float Bs[KC][BCOLS];
    int tid  = threadIdx.x;
    int row0 = blockIdx.x * 32;
    int rg = tid >> 5;   // warp id -> 4 rows each
    int ct = tid & 31;   // lane -> 11 cols stride 32
    float acc[4][11];
    #pragma unroll
    for (int i = 0; i < 4; i++)
        #pragma unroll
        for (int j = 0; j < 11; j++) acc[i][j] = 0.f;

    for (int kc = 0; kc < DIN; kc += KC) {
        for (int idx = tid; idx < 32 * (KC / 4); idx += 256) {
            int r = idx >> 2, q = idx & 3;
            int gr = row0 + r;
            float4 f = (gr < NN)
                ? *(const float4*)(feat + gr * DIN + kc + q * 4)
                : make_float4(0.f, 0.f, 0.f, 0.f);
            As[r][q * 4 + 0] = f.x; As[r][q * 4 + 1] = f.y;
            As[r][q * 4 + 2] = f.z; As[r][q * 4 + 3] = f.w;
        }
        for (int idx = tid; idx < KC * (BCOLS / 4); idx += 256) {
            int kk = idx / (BCOLS / 4), q = idx - kk * (BCOLS / 4);
            *((float4*)&Bs[kk][q * 4]) =
                *(const float4*)(g_B + (kc + kk) * BCOLS + q * 4);
        }
        __syncthreads();
        #pragma unroll
        for (int kk = 0; kk < KC; kk++) {
            float a[4], bb[11];
            #pragma unroll
            for (int i = 0; i < 4; i++) a[i] = As[rg * 4 + i][kk];
            #pragma unroll
            for (int j = 0; j < 11; j++) bb[j] = Bs[kk][ct + 32 * j];
            #pragma unroll
            for (int i = 0; i < 4; i++)
                #pragma unroll
                for (int j = 0; j < 11; j++) acc[i][j] += a[i] * bb[j];
        }
        __syncthreads();
    }
    #pragma unroll
    for (int i = 0; i < 4; i++) {
        int r = row0 + rg * 4 + i;
        if (r >= NN) continue;
        #pragma unroll
        for (int j = 0; j < 11; j++) {
            int c = ct + 32 * j;
            float v = acc[i][j];
            if (c < DGG) {
                g_zjh[r * DGG + c] = __float2half(v);
            } else if (c < 320) {
                int jj = c - DGG;
                float o = fmaxf(v + b[jj], 0.f);
                if (jj < DOUT) g_f0[r * DOUT + jj] = o;
                else           g_f1h[r * DOUT + (jj - DOUT)] = __float2half(o);
            } else if (c < 328) {
                g_fzh[r * HH + (c - 320)] = __float2half(v);
            }
        }
    }
}

// ---------------- attention scalars ----------------
__device__ __forceinline__ float leaky(float x) {
    return x >= 0.f ? x : 0.2f * x;
}

__global__ void k_att(const float* __restrict__ att) {
    int i = blockIdx.x * blockDim.x + threadIdx.x;
    if (i >= NN * HH) return;
    int n = i >> 3, h = i & 7;
    float s = 0.f, t = 0.f;
    const float*  f0p = g_f0  + n * DOUT + h * DHH;
    const __half* f1p = g_f1h + n * DOUT + h * DHH;
    const float*  ap  = att + h * (2 * DHH);
    #pragma unroll
    for (int k = 0; k < DHH; k++) {
        s += f0p[k] * ap[k];
        t += __half2float(f1p[k]) * ap[DHH + k];
    }
    g_aself[i]  = leaky(s);
    g_aneigh[i] = leaky(t);
}

// ---------------- main per-node kernel ----------------
// 4 warps; warp w handles edges i = w, w+4, ... ; lane l covers features 4l..4l+3
__global__ void __launch_bounds__(128, 12)
k_main(const float* __restrict__ feat,
       const float* __restrict__ wg,       // [320,8]
       const float* __restrict__ scale,    // [2,128]
       const float* __restrict__ offset,   // [2,128]
       float* __restrict__ out) {
    __shared__ unsigned long long s_e[128];
    __shared__ float s_agg[4][DOUT];
    __shared__ float s_z[4][DGG];
    __shared__ float s_gn[4][HH];
    __shared__ float wred[4][8];
    __shared__ float s_gate[8];
    __shared__ float red[4][4];
    __shared__ float stats[4];

    int n    = blockIdx.x;
    int tid  = threadIdx.x;
    int w    = tid >> 5;
    int lane = tid & 31;

    int e0 = g_ptr[n], e1 = g_ptr[n + 1];
    int deg = e1 - e0;

    int   hlane = lane >> 2;                     // head of this lane's 4 features
    float aself = g_aself[n * HH + hlane];

    float4 acc = make_float4(0.f, 0.f, 0.f, 0.f);
    float4 zm4 = make_float4(-CUDART_INF_F, -CUDART_INF_F, -CUDART_INF_F, -CUDART_INF_F);
    float4 gn4 = make_float4(0.f, 0.f, 0.f, 0.f);

    for (int chunk = e0; chunk < e1; chunk += 128) {
        int m = min(128, e1 - chunk);
        if (tid < m) s_e[tid] = g_edge[chunk + tid];
        __syncthreads();
        #pragma unroll 2
        for (int i = w; i < m; i += 4) {
            unsigned long long pk = s_e[i];
            int   c = (int)(unsigned)(pk & 0xffffffffull);
            float v = __uint_as_float((unsigned)(pk >> 32));
            float a = (aself + g_aneigh[c * HH + hlane]) * v;
            uint2 fr = *((const uint2*)(g_f1h + c * DOUT) + lane);   // 4 halves
            float2 f01 = __half22float2(*(const __half2*)&fr.x);
            float2 f23 = __half22float2(*(const __half2*)&fr.y);
            acc.x += a * f01.x; acc.y += a * f01.y;
            acc.z += a * f23.x; acc.w += a * f23.y;
            if (lane < 16) {
                uint2 zr = *((const uint2*)(g_zjh + c * DGG) + lane);
                float2 z01 = __half22float2(*(const __half2*)&zr.x);
                float2 z23 = __half22float2(*(const __half2*)&zr.y);
                zm4.x = fmaxf(zm4.x, z01.x); zm4.y = fmaxf(zm4.y, z01.y);
                zm4.z = fmaxf(zm4.z, z23.x); zm4.w = fmaxf(zm4.w, z23.y);
            }
            if (lane < 2) {
                uint2 gr = *((const uint2*)(g_fzh + c * HH) + lane);
                float2 g01 = __half22float2(*(const __half2*)&gr.x);
                float2 g23 = __half22float2(*(const __half2*)&gr.y);
                gn4.x += v * g01.x; gn4.y += v * g01.y;
                gn4.z += v * g23.x; gn4.w += v * g23.y;
            }
        }
        __syncthreads();
    }

    // stash per-warp partials
    ((float4*)s_agg[w])[lane] = acc;
    if (lane < 16) ((float4*)s_z[w])[lane] = zm4;
    if (lane < 2)  ((float4*)s_gn[w])[lane] = gn4;
    __syncthreads();

    int j = tid;                      // feature index 0..127
    int h = j >> 4;
    int wid = w;

    float aggj = s_agg[0][j] + s_agg[1][j] + s_agg[2][j] + s_agg[3][j];

    // ---- gate[h] = feat.wg[0:128] + zmax.wg[128:192] + nmean-lin ----
    float part[8];
    #pragma unroll
    for (int hh = 0; hh < 8; hh++) part[hh] = 0.f;
    {
        float z = feat[n * DIN + j];
        const float* wr = wg + j * 8;
        #pragma unroll
        for (int hh = 0; hh < 8; hh++) part[hh] += z * wr[hh];
    }
    if (j < DGG) {
        float zmj = fmaxf(fmaxf(s_z[0][j], s_z[1][j]), fmaxf(s_z[2][j], s_z[3][j]));
        float z = (deg > 0) ? zmj : 0.f;
        const float* wr = wg + (128 + j) * 8;
        #pragma unroll
        for (int hh = 0; hh < 8; hh++) part[hh] += z * wr[hh];
    }
    #pragma unroll
    for (int hh = 0; hh < 8; hh++) {
        #pragma unroll
        for (int off = 16; off > 0; off >>= 1)
            part[hh] += __shfl_down_sync(0xffffffffu, part[hh], off);
    }
    if (lane == 0) {
        #pragma unroll
        for (int hh = 0; hh < 8; hh++) wred[wid][hh] = part[hh];
    }
    __syncthreads();
    if (j < 8) {
        float gnm = s_gn[0][j] + s_gn[1][j] + s_gn[2][j] + s_gn[3][j];
        s_gate[j] = wred[0][j] + wred[1][j] + wred[2][j] + wred[3][j] + gnm;
    }
    __syncthreads();

    // ---- norm + output ----
    float h0j = g_f0[n * DOUT + j];
    float h1j = aggj * s_gate[h];

    float s0 = h0j, q0 = h0j * h0j, s1 = h1j, q1 = h1j * h1j;
    #pragma unroll
    for (int off = 16; off > 0; off >>= 1) {
        s0 += __shfl_down_sync(0xffffffffu, s0, off);
        q0 += __shfl_down_sync(0xffffffffu, q0, off);
        s1 += __shfl_down_sync(0xffffffffu, s1, off);
        q1 += __shfl_down_sync(0xffffffffu, q1, off);
    }
    if (lane == 0) {
        red[wid][0] = s0; red[wid][1] = q0; red[wid][2] = s1; red[wid][3] = q1;
    }
    __syncthreads();
    if (j == 0) {
        float S0 = 0, Q0 = 0, S1 = 0, Q1 = 0;
        #pragma unroll
        for (int ww = 0; ww < 4; ww++) {
            S0 += red[ww][0]; Q0 += red[ww][1]; S1 += red[ww][2]; Q1 += red[ww][3];
        }
        float mu0 = S0 * (1.f / DOUT);
        float mu1 = S1 * (1.f / DOUT);
        float v0  = Q0 * (1.f / DOUT) - mu0 * mu0 + 1e-9f;
        float v1  = Q1 * (1.f / DOUT) - mu1 * mu1 + 1e-9f;
        stats[0] = mu0; stats[1] = rsqrtf(v0);
        stats[2] = mu1; stats[3] = rsqrtf(v1);
    }
    __syncthreads();

    float o0 = (h0j - stats[0]) * stats[1] * scale[j]        + offset[j];
    float o1 = (h1j - stats[2]) * stats[3] * scale[DOUT + j] + offset[DOUT + j];
    out[n * DOUT + j] = o0 + o1;
}

// ---------------- launch ----------------
extern "C" void kernel_launch(void* const* d_in, const int* in_sizes, int n_in,
                              void* d_out, int out_size) {
    const int*   row    = (const int*)d_in[0];
    const int*   col    = (const int*)d_in[1];
    const float* val    = (const float*)d_in[2];
    const float* feat   = (const float*)d_in[3];
    const float* W      = (const float*)d_in[4];
    const float* b      = (const float*)d_in[5];
    const float* att    = (const float*)d_in[6];
    const float* offset = (const float*)d_in[7];
    const float* scale  = (const float*)d_in[8];
    const float* wg     = (const float*)d_in[9];
    const float* wpg    = (const float*)d_in[10];
    float* out = (float*)d_out;

    // CSR build
    k_zero_cnt<<<(NN + 255) / 256, 256>>>();
    k_hist<<<(EE + 255) / 256, 256>>>(row);
    k_scan<<<1, 1024>>>();
    k_scatter<<<(EE + 255) / 256, 256>>>(row, col, val);

    // Dense projections
    k_pack<<<(DIN * BCOLS + 255) / 256, 256>>>(wpg, W, wg);
    k_gemm<<<(NN + 31) / 32, 256>>>(feat, b);
    k_att<<<(NN * HH + 255) / 256, 256>>>(att);

    // Fused aggregate + gate + norm + output
    k_main<<<NN, 128>>>(feat, wg, scale, offset, out);
}

// round 7
// speedup vs baseline: 1.2590x; 1.2590x over previous
#include <cuda_runtime.h>
#include <math_constants.h>

// Problem constants (fixed by the reference setup)
#define NN    50000
#define EE    1600000
#define DIN   128
#define DOUT  128
#define HH    8
#define DHH   16
#define DGG   64
#define BCOLS 352   // padded: 64 zj | 128 f0 | 128 f1 | 8 fz | 24 pad

// ---------------- device scratch (no allocation allowed) ----------------
__device__ float  g_B[DIN * BCOLS];    // prepacked GEMM B
__device__ float  g_zj[NN * DGG];      // feat @ Wpg              [N,64]
__device__ float  g_f0[NN * DOUT];     // relu(feat@W0 + b0)      [N,128]
__device__ float  g_f1[NN * DOUT];     // relu(feat@W1 + b1)      [N,128]
__device__ float  g_fz[NN * HH];       // feat @ wg[192:320]      [N,8]
__device__ float  g_aself[NN * HH];    // leaky(f0 . att_self)    [N,8]
__device__ float  g_aneigh[NN * HH];   // leaky(f1 . att_neigh)   [N,8]
__device__ int    g_cnt[NN];
__device__ int    g_ptr[NN + 1];
__device__ int    g_pos[NN];
__device__ unsigned long long g_edge[EE];  // packed (val<<32 | col), CSR order

// ---------------- CSR build ----------------
__global__ void k_zero_cnt() {
    int i = blockIdx.x * blockDim.x + threadIdx.x;
    if (i < NN) g_cnt[i] = 0;
}

__global__ void k_hist(const int* __restrict__ row) {
    int i = blockIdx.x * blockDim.x + threadIdx.x;
    if (i < EE) atomicAdd(&g_cnt[row[i]], 1);
}

__global__ void k_scan() {
    __shared__ int wsum[32];
    __shared__ int s_carry;
    int tid  = threadIdx.x;
    int lane = tid & 31;
    int wid  = tid >> 5;
    if (tid == 0) s_carry = 0;
    __syncthreads();
    for (int base = 0; base < NN; base += 1024) {
        int i = base + tid;
        int x = (i < NN) ? g_cnt[i] : 0;
        int v = x;
        #pragma unroll
        for (int off = 1; off < 32; off <<= 1) {
            int t = __shfl_up_sync(0xffffffffu, v, off);
            if (lane >= off) v += t;
        }
        if (lane == 31) wsum[wid] = v;
        __syncthreads();
        if (wid == 0) {
            int s = wsum[lane];
            #pragma unroll
            for (int off = 1; off < 32; off <<= 1) {
                int t = __shfl_up_sync(0xffffffffu, s, off);
                if (lane >= off) s += t;
            }
            wsum[lane] = s;
        }
        __syncthreads();
        int incl  = v + (wid > 0 ? wsum[wid - 1] : 0);
        int carry = s_carry;
        if (i < NN) {
            int e = carry + incl - x;
            g_ptr[i] = e;
            g_pos[i] = e;
        }
        __syncthreads();
        if (tid == 1023) s_carry = carry + incl;
        __syncthreads();
    }
    if (tid == 0) g_ptr[NN] = s_carry;
}

__global__ void k_scatter(const int* __restrict__ row,
                          const int* __restrict__ col,
                          const float* __restrict__ val) {
    int i = blockIdx.x * blockDim.x + threadIdx.x;
    if (i < EE) {
        int p = atomicAdd(&g_pos[row[i]], 1);
        unsigned long long pk =
            ((unsigned long long)__float_as_uint(val[i]) << 32) |
            (unsigned long long)(unsigned)col[i];
        g_edge[p] = pk;
    }
}

// ---------------- pack B once: [128][352] ----------------
__global__ void k_pack(const float* __restrict__ Wpg,
                       const float* __restrict__ W,
                       const float* __restrict__ wg) {
    int idx = blockIdx.x * blockDim.x + threadIdx.x;
    if (idx >= DIN * BCOLS) return;
    int k = idx / BCOLS, c = idx - k * BCOLS;
    float w = 0.f;
    if (c < DGG) {
        w = Wpg[k * DGG + c];
    } else if (c < 320) {
        int j  = c - DGG;
        int o  = j >> 7;
        int jj = j & 127;
        int h  = jj >> 4, kb = jj & 15;
        w = W[((o * HH + h) * DIN + k) * DHH + kb];
    } else if (c < 328) {
        w = wg[(192 + k) * HH + (c - 320)];
    }
    g_B[idx] = w;
}

// ---------------- GEMM: [N,128] x [128,352] (packed B) ----------------
// __launch_bounds__(256,2): 128-reg budget -> 44 fp32 accumulators live with
// NO spills (the R4 (256,4)=64-reg cap forced per-iteration LDL/STL).
#define KC 16
__global__ void __launch_bounds__(256, 2)
k_gemm(const float* __restrict__ feat, const float* __restrict__ b) {
    __shared__ float As[32][KC + 1];
    __shared__ float Bs[KC][BCOLS];
    int tid  = threadIdx.x;
    int row0 = blockIdx.x * 32;
    int rg = tid >> 5;   // warp id -> 4 rows each
    int ct = tid & 31;   // lane -> 11 cols stride 32
    float acc[4][11];
    #pragma unroll
    for (int i = 0; i < 4; i++)
        #pragma unroll
        for (int j = 0; j < 11; j++) acc[i][j] = 0.f;

    for (int kc = 0; kc < DIN; kc += KC) {
        for (int idx = tid; idx < 32 * (KC / 4); idx += 256) {
            int r = idx >> 2, q = idx & 3;
            int gr = row0 + r;
            float4 f = (gr < NN)
                ? *(const float4*)(feat + gr * DIN + kc + q * 4)
                : make_float4(0.f, 0.f, 0.f, 0.f);
            As[r][q * 4 + 0] = f.x; As[r][q * 4 + 1] = f.y;
            As[r][q * 4 + 2] = f.z; As[r][q * 4 + 3] = f.w;
        }
        for (int idx = tid; idx < KC * (BCOLS / 4); idx += 256) {
            int kk = idx / (BCOLS / 4), q = idx - kk * (BCOLS / 4);
            *((float4*)&Bs[kk][q * 4]) =
                *(const float4*)(g_B + (kc + kk) * BCOLS + q * 4);
        }
        __syncthreads();
        #pragma unroll
        for (int kk = 0; kk < KC; kk++) {
            float a[4], bb[11];
            #pragma unroll
            for (int i = 0; i < 4; i++) a[i] = As[rg * 4 + i][kk];
            #pragma unroll
            for (int j = 0; j < 11; j++) bb[j] = Bs[kk][ct + 32 * j];
            #pragma unroll
            for (int i = 0; i < 4; i++)
                #pragma unroll
                for (int j = 0; j < 11; j++) acc[i][j] += a[i] * bb[j];
        }
        __syncthreads();
    }
    #pragma unroll
    for (int i = 0; i < 4; i++) {
        int r = row0 + rg * 4 + i;
        if (r >= NN) continue;
        #pragma unroll
        for (int j = 0; j < 11; j++) {
            int c = ct + 32 * j;
            float v = acc[i][j];
            if (c < DGG) {
                g_zj[r * DGG + c] = v;
            } else if (c < 320) {
                int jj = c - DGG;
                float o = fmaxf(v + b[jj], 0.f);
                if (jj < DOUT) g_f0[r * DOUT + jj] = o;
                else           g_f1[r * DOUT + (jj - DOUT)] = o;
            } else if (c < 328) {
                g_fz[r * HH + (c - 320)] = v;
            }
        }
    }
}

// ---------------- attention scalars ----------------
__device__ __forceinline__ float leaky(float x) {
    return x >= 0.f ? x : 0.2f * x;
}

__global__ void k_att(const float* __restrict__ att) {
    int i = blockIdx.x * blockDim.x + threadIdx.x;
    if (i >= NN * HH) return;
    int n = i >> 3, h = i & 7;
    float s = 0.f, t = 0.f;
    const float* f0p = g_f0 + n * DOUT + h * DHH;
    const float* f1p = g_f1 + n * DOUT + h * DHH;
    const float* ap  = att + h * (2 * DHH);
    #pragma unroll
    for (int k = 0; k < DHH; k++) {
        s += f0p[k] * ap[k];
        t += f1p[k] * ap[DHH + k];
    }
    g_aself[i]  = leaky(s);
    g_aneigh[i] = leaky(t);
}

// ---------------- main per-node kernel ----------------
// 4 warps; warp w handles edges i = w, w+4, ... ; lane l covers features 4l..4l+3
__global__ void __launch_bounds__(128, 12)
k_main(const float* __restrict__ feat,
       const float* __restrict__ wg,       // [320,8]
       const float* __restrict__ scale,    // [2,128]
       const float* __restrict__ offset,   // [2,128]
       float* __restrict__ out) {
    __shared__ unsigned long long s_e[128];
    __shared__ float s_agg[4][DOUT];
    __shared__ float s_z[4][DGG];
    __shared__ float s_gn[4][HH];
    __shared__ float wred[4][8];
    __shared__ float s_gate[8];
    __shared__ float red[4][4];
    __shared__ float stats[4];

    int n    = blockIdx.x;
    int tid  = threadIdx.x;
    int w    = tid >> 5;
    int lane = tid & 31;

    int e0 = g_ptr[n], e1 = g_ptr[n + 1];
    int deg = e1 - e0;

    int   hlane = lane >> 2;                     // head of this lane's 4 features
    float aself = g_aself[n * HH + hlane];

    float4 acc = make_float4(0.f, 0.f, 0.f, 0.f);
    float4 zm4 = make_float4(-CUDART_INF_F, -CUDART_INF_F, -CUDART_INF_F, -CUDART_INF_F);
    float4 gn4 = make_float4(0.f, 0.f, 0.f, 0.f);

    for (int chunk = e0; chunk < e1; chunk += 128) {
        int m = min(128, e1 - chunk);
        if (tid < m) s_e[tid] = g_edge[chunk + tid];
        __syncthreads();
        #pragma unroll 2
        for (int i = w; i < m; i += 4) {
            unsigned long long pk = s_e[i];
            int   c = (int)(unsigned)(pk & 0xffffffffull);
            float v = __uint_as_float((unsigned)(pk >> 32));
            float a = (aself + g_aneigh[c * HH + hlane]) * v;
            float4 f = *((const float4*)(g_f1 + c * DOUT) + lane);
            acc.x += a * f.x; acc.y += a * f.y;
            acc.z += a * f.z; acc.w += a * f.w;
            if (lane < 16) {
                float4 z = *((const float4*)(g_zj + c * DGG) + lane);
                zm4.x = fmaxf(zm4.x, z.x); zm4.y = fmaxf(zm4.y, z.y);
                zm4.z = fmaxf(zm4.z, z.z); zm4.w = fmaxf(zm4.w, z.w);
            }
            if (lane < 2) {
                float4 g = *((const float4*)(g_fz + c * HH) + lane);
                gn4.x += v * g.x; gn4.y += v * g.y;
                gn4.z += v * g.z; gn4.w += v * g.w;
            }
        }
        __syncthreads();
    }

    // stash per-warp partials
    ((float4*)s_agg[w])[lane] = acc;
    if (lane < 16) ((float4*)s_z[w])[lane] = zm4;
    if (lane < 2)  ((float4*)s_gn[w])[lane] = gn4;
    __syncthreads();

    int j = tid;                      // feature index 0..127
    int h = j >> 4;
    int wid = w;

    float aggj = s_agg[0][j] + s_agg[1][j] + s_agg[2][j] + s_agg[3][j];

    // ---- gate[h] = feat.wg[0:128] + zmax.wg[128:192] + nmean-lin ----
    float part[8];
    #pragma unroll
    for (int hh = 0; hh < 8; hh++) part[hh] = 0.f;
    {
        float z = feat[n * DIN + j];
        const float* wr = wg + j * 8;
        #pragma unroll
        for (int hh = 0; hh < 8; hh++) part[hh] += z * wr[hh];
    }
    if (j < DGG) {
        float zmj = fmaxf(fmaxf(s_z[0][j], s_z[1][j]), fmaxf(s_z[2][j], s_z[3][j]));
        float z = (deg > 0) ? zmj : 0.f;
        const float* wr = wg + (128 + j) * 8;
        #pragma unroll
        for (int hh = 0; hh < 8; hh++) part[hh] += z * wr[hh];
    }
    #pragma unroll
    for (int hh = 0; hh < 8; hh++) {
        #pragma unroll
        for (int off = 16; off > 0; off >>= 1)
            part[hh] += __shfl_down_sync(0xffffffffu, part[hh], off);
    }
    if (lane == 0) {
        #pragma unroll
        for (int hh = 0; hh < 8; hh++) wred[wid][hh] = part[hh];
    }
    __syncthreads();
    if (j < 8) {
        float gnm = s_gn[0][j] + s_gn[1][j] + s_gn[2][j] + s_gn[3][j];
        s_gate[j] = wred[0][j] + wred[1][j] + wred[2][j] + wred[3][j] + gnm;
    }
    __syncthreads();

    // ---- norm + output ----
    float h0j = g_f0[n * DOUT + j];
    float h1j = aggj * s_gate[h];

    float s0 = h0j, q0 = h0j * h0j, s1 = h1j, q1 = h1j * h1j;
    #pragma unroll
    for (int off = 16; off > 0; off >>= 1) {
        s0 += __shfl_down_sync(0xffffffffu, s0, off);
        q0 += __shfl_down_sync(0xffffffffu, q0, off);
        s1 += __shfl_down_sync(0xffffffffu, s1, off);
        q1 += __shfl_down_sync(0xffffffffu, q1, off);
    }
    if (lane == 0) {
        red[wid][0] = s0; red[wid][1] = q0; red[wid][2] = s1; red[wid][3] = q1;
    }
    __syncthreads();
    if (j == 0) {
        float S0 = 0, Q0 = 0, S1 = 0, Q1 = 0;
        #pragma unroll
        for (int ww = 0; ww < 4; ww++) {
            S0 += red[ww][0]; Q0 += red[ww][1]; S1 += red[ww][2]; Q1 += red[ww][3];
        }
        float mu0 = S0 * (1.f / DOUT);
        float mu1 = S1 * (1.f / DOUT);
        float v0  = Q0 * (1.f / DOUT) - mu0 * mu0 + 1e-9f;
        float v1  = Q1 * (1.f / DOUT) - mu1 * mu1 + 1e-9f;
        stats[0] = mu0; stats[1] = rsqrtf(v0);
        stats[2] = mu1; stats[3] = rsqrtf(v1);
    }
    __syncthreads();

    float o0 = (h0j - stats[0]) * stats[1] * scale[j]        + offset[j];
    float o1 = (h1j - stats[2]) * stats[3] * scale[DOUT + j] + offset[DOUT + j];
    out[n * DOUT + j] = o0 + o1;
}

// ---------------- launch ----------------
extern "C" void kernel_launch(void* const* d_in, const int* in_sizes, int n_in,
                              void* d_out, int out_size) {
    const int*   row    = (const int*)d_in[0];
    const int*   col    = (const int*)d_in[1];
    const float* val    = (const float*)d_in[2];
    const float* feat   = (const float*)d_in[3];
    const float* W      = (const float*)d_in[4];
    const float* b      = (const float*)d_in[5];
    const float* att    = (const float*)d_in[6];
    const float* offset = (const float*)d_in[7];
    const float* scale  = (const float*)d_in[8];
    const float* wg     = (const float*)d_in[9];
    const float* wpg    = (const float*)d_in[10];
    float* out = (float*)d_out;

    // CSR build
    k_zero_cnt<<<(NN + 255) / 256, 256>>>();
    k_hist<<<(EE + 255) / 256, 256>>>(row);
    k_scan<<<1, 1024>>>();
    k_scatter<<<(EE + 255) / 256, 256>>>(row, col, val);

    // Dense projections
    k_pack<<<(DIN * BCOLS + 255) / 256, 256>>>(wpg, W, wg);
    k_gemm<<<(NN + 31) / 32, 256>>>(feat, b);
    k_att<<<(NN * HH + 255) / 256, 256>>>(att);

    // Fused aggregate + gate + norm + output
    k_main<<<NN, 128>>>(feat, wg, scale, offset, out);
}